// round 14
// baseline (speedup 1.0000x reference)
#include <cuda_runtime.h>
#include <cuda_bf16.h>
#include <string.h>
#include <stdint.h>

#define BB 8
#define TT 8192
#define SN 8192
#define FF 64
#define DD 64
#define MMF 128
#define TWOM 256
#define EPSF 1e-9f
#define SCALEF 0.0625f   /* 1/sqrt(2*128) */
#define KVW 66           /* g_kv row stride: col 64 = normalizer, 65 pad */

#define NBLK 148
#define NTILES 1024      /* 64-row tiles, 128 per batch */
#define QTIL 512         /* 128-row t-tiles, 64 per batch */
#define QNB 148

__device__ float g_part[(size_t)NBLK * 2 * TWOM * KVW];
__device__ float g_kv[BB * TWOM * KVW];

static __device__ __forceinline__ uint32_t smem_u32(const void* p) {
    uint32_t a;
    asm("{ .reg .u64 t; cvta.to.shared.u64 t, %1; cvt.u32.u64 %0, t; }" : "=r"(a) : "l"(p));
    return a;
}
static __device__ __forceinline__ void ldsm_x4(uint32_t& r0, uint32_t& r1,
                                               uint32_t& r2, uint32_t& r3, uint32_t addr) {
    asm volatile("ldmatrix.sync.aligned.m8n8.x4.shared.b16 {%0,%1,%2,%3}, [%4];"
                 : "=r"(r0), "=r"(r1), "=r"(r2), "=r"(r3) : "r"(addr));
}
static __device__ __forceinline__ void ldsm_x4_t(uint32_t& r0, uint32_t& r1,
                                                 uint32_t& r2, uint32_t& r3, uint32_t addr) {
    asm volatile("ldmatrix.sync.aligned.m8n8.x4.trans.shared.b16 {%0,%1,%2,%3}, [%4];"
                 : "=r"(r0), "=r"(r1), "=r"(r2), "=r"(r3) : "r"(addr));
}
static __device__ __forceinline__ void mma_bf16(float* c,
                                                uint32_t a0, uint32_t a1, uint32_t a2, uint32_t a3,
                                                uint32_t b0, uint32_t b1) {
    asm volatile("mma.sync.aligned.m16n8k16.row.col.f32.bf16.bf16.f32 "
                 "{%0,%1,%2,%3}, {%4,%5,%6,%7}, {%8,%9}, {%0,%1,%2,%3};"
                 : "+f"(c[0]), "+f"(c[1]), "+f"(c[2]), "+f"(c[3])
                 : "r"(a0), "r"(a1), "r"(a2), "r"(a3), "r"(b0), "r"(b1));
}
static __device__ __forceinline__ uint32_t pack_hi(float e0, float e1) {
    __nv_bfloat162 hp;
    hp.x = __float2bfloat16_rn(e0); hp.y = __float2bfloat16_rn(e1);
    uint32_t u; memcpy(&u, &hp, 4); return u;
}
static __device__ __forceinline__ uint32_t pack_lo(float e0, float e1, uint32_t hi) {
    __nv_bfloat162 hp; memcpy(&hp, &hi, 4);
    __nv_bfloat162 lp;
    lp.x = __float2bfloat16_rn(e0 - __bfloat162float(hp.x));
    lp.y = __float2bfloat16_rn(e1 - __bfloat162float(hp.y));
    uint32_t u; memcpy(&u, &lp, 4); return u;
}

#define BAR_SYNC(id, cnt)   asm volatile("bar.sync %0, %1;"   :: "r"(id), "r"(cnt) : "memory")
#define BAR_ARRIVE(id, cnt) asm volatile("bar.arrive %0, %1;" :: "r"(id), "r"(cnt) : "memory")

/* ---------- kv smem (bytes): double-buffered A / BT / XT / ssq ---------- */
#define KA_H(buf)  ((buf) * 73728)               /* phi hi [256][144B] */
#define KA_L(buf)  ((buf) * 73728 + 36864)       /* phi lo */
#define KBT(buf)   (147456 + (buf) * 17408)      /* v packed BT [64][68w] */
#define KXT(buf)   (182272 + (buf) * 17408)      /* x packed BT [64][68w] */
#define KSQ(buf)   (217088 + (buf) * 256)        /* ssq [64] */
#define KV_SMEM    217600

/* ---------- qkv smem (round-13 proven) ---------- */
#define QOFF_PH 0
#define QOFF_PL 36864
#define QOFF_BT 73728
#define QOFF_XT 148608
#define QOFF_SQ 166016
#define QOFF_NS 166272
#define QOFF_NPB 166528
#define QSMEM   168640

// ---------------------------------------------------------------------------
// Kernel 1: warp-specialized kv. Warps 0-7 produce (stage + phi-MMA + exp +
// A/BT stores), warps 8-15 consume (kv-MMA, persistent acc over 32 features
// each). Double-buffered handoff via named barriers FULL(1,2)/EMPTY(3,4).
// ---------------------------------------------------------------------------
__global__ __launch_bounds__(512, 1)
void kv_kernel(const float* __restrict__ key,
               const float* __restrict__ value,
               const float* __restrict__ omega) {
    extern __shared__ char smc[];
    const uint32_t sb = smem_u32(smc);

    const int tid = threadIdx.x;
    const int blk = blockIdx.x;
    const int tb = (blk * NTILES) / NBLK;
    const int te = ((blk + 1) * NTILES) / NBLK;

    /* omega -> bf16 hi/lo into A buffer 0 ([m][f], 144B stride) */
    {
        const float4* om4 = (const float4*)omega;
#pragma unroll
        for (int q = 0; q < 4; ++q) {
            int idx = tid + q * 512;
            float4 v = om4[idx];
            int m = idx >> 4, f = (idx & 15) * 4;
            uint32_t h01 = pack_hi(v.x, v.y), h23 = pack_hi(v.z, v.w);
            uint32_t* wh = (uint32_t*)(smc + KA_H(0) + m * 144 + f * 2);
            uint32_t* wl = (uint32_t*)(smc + KA_L(0) + m * 144 + f * 2);
            wh[0] = h01; wh[1] = h23;
            wl[0] = pack_lo(v.x, v.y, h01); wl[1] = pack_lo(v.z, v.w, h23);
        }
    }
    __syncthreads();

    const int w = tid >> 5, lane = tid & 31;
    const int gid = lane >> 2, tg = lane & 3;
    const int quad = lane >> 3, lrow = lane & 7;
    const int arow = lrow + (quad & 1) * 8;
    const int acolb = (quad >> 1) * 16;
    const uint32_t xq_lane = (uint32_t)((lane & 7) * 272 + ((lane >> 3) & 1) * 16 + (lane >> 4) * 128);

    if (w < 8) {
        /* ============================ PRODUCER ============================ */
        const int ptid = tid;             /* 0..255 */
        const int pcol = ptid & 15;
        const int prow = ptid >> 4;

        /* hoist omega A fragments for own m-tile (mt = w) */
        uint32_t wfh[4][4], wfl[4][4];
        {
            uint32_t obase = sb + KA_H(0) + (uint32_t)((w * 16 + arow) * 144 + acolb);
#pragma unroll
            for (int kt = 0; kt < 4; ++kt) {
                ldsm_x4(wfh[kt][0], wfh[kt][1], wfh[kt][2], wfh[kt][3], obase + kt * 32);
                ldsm_x4(wfl[kt][0], wfl[kt][1], wfl[kt][2], wfl[kt][3], obase + 36864 + kt * 32);
            }
        }

        float4 px[4], pv[4];
        {
            int t = tb, b = t >> 7, s0 = (t & 127) * 64;
            const float4* kp = (const float4*)(key   + ((size_t)b * SN + s0) * FF);
            const float4* vp = (const float4*)(value + ((size_t)b * SN + s0) * FF);
#pragma unroll
            for (int q = 0; q < 4; ++q) px[q] = kp[ptid + q * 256];
#pragma unroll
            for (int q = 0; q < 2; ++q) {
                int p = prow + q * 16;
                pv[2 * q]     = vp[(2 * p) * 16 + pcol];
                pv[2 * q + 1] = vp[(2 * p + 1) * 16 + pcol];
            }
        }

        for (int t = tb; t < te; ++t) {
            const int buf = t & 1;
            if (t - tb >= 2) BAR_SYNC(3 + buf, 512);   /* consumers done with buf */

            /* stage XT + ssq */
#pragma unroll
            for (int q = 0; q < 4; ++q) {
                int r = prow + q * 16;
                float4 xv = px[q];
                int p0 = pcol * 2;
                uint32_t h0 = pack_hi(xv.x, xv.y), h1 = pack_hi(xv.z, xv.w);
                uint32_t l0 = pack_lo(xv.x, xv.y, h0), l1 = pack_lo(xv.z, xv.w, h1);
                *(uint2*)(smc + KXT(buf) + (size_t)(r * 68 + p0) * 4)      = make_uint2(h0, h1);
                *(uint2*)(smc + KXT(buf) + (size_t)(r * 68 + 32 + p0) * 4) = make_uint2(l0, l1);
                float sq = xv.x * xv.x + xv.y * xv.y + xv.z * xv.z + xv.w * xv.w;
#pragma unroll
                for (int d = 1; d < 16; d <<= 1)
                    sq += __shfl_xor_sync(0xffffffffu, sq, d);
                if (pcol == 0) ((float*)(smc + KSQ(buf)))[r] = 0.5f * sq;
            }
            /* stage BT (v packed, direct from registers) */
#pragma unroll
            for (int q = 0; q < 2; ++q) {
                int p = prow + q * 16;
                float4 va = pv[2 * q], vb = pv[2 * q + 1];
                float a4[4] = {va.x, va.y, va.z, va.w};
                float b4[4] = {vb.x, vb.y, vb.z, vb.w};
#pragma unroll
                for (int j = 0; j < 4; ++j) {
                    int n = pcol * 4 + j;
                    uint32_t hw = pack_hi(a4[j], b4[j]);
                    *(uint32_t*)(smc + KBT(buf) + (size_t)(n * 68 + p) * 4)      = hw;
                    *(uint32_t*)(smc + KBT(buf) + (size_t)(n * 68 + 32 + p) * 4) = pack_lo(a4[j], b4[j], hw);
                }
            }
            /* prefetch next tile */
            if (t + 1 < te) {
                int tn = t + 1, b = tn >> 7, s0 = (tn & 127) * 64;
                const float4* kp = (const float4*)(key   + ((size_t)b * SN + s0) * FF);
                const float4* vp = (const float4*)(value + ((size_t)b * SN + s0) * FF);
#pragma unroll
                for (int q = 0; q < 4; ++q) px[q] = kp[ptid + q * 256];
#pragma unroll
                for (int q = 0; q < 2; ++q) {
                    int p = prow + q * 16;
                    pv[2 * q]     = vp[(2 * p) * 16 + pcol];
                    pv[2 * q + 1] = vp[(2 * p + 1) * 16 + pcol];
                }
            }
            BAR_SYNC(5, 256);   /* XT/ssq visible to all producers */

            /* phi-MMA + exp + A store: warp = m-tile w, loop r-tiles 0..7 */
            const uint32_t xtB = sb + KXT(buf) + xq_lane;
            const float* ssq = (const float*)(smc + KSQ(buf));
#pragma unroll
            for (int ntr = 0; ntr < 8; ++ntr) {
                float wa[4] = {0.f, 0.f, 0.f, 0.f};
#pragma unroll
                for (int kt = 0; kt < 4; ++kt) {
                    uint32_t bh0, bh1, bl0, bl1;
                    ldsm_x4(bh0, bh1, bl0, bl1, xtB + ntr * 2176 + kt * 32);
                    mma_bf16(wa, wfh[kt][0], wfh[kt][1], wfh[kt][2], wfh[kt][3], bh0, bh1);
                    mma_bf16(wa, wfl[kt][0], wfl[kt][1], wfl[kt][2], wfl[kt][3], bh0, bh1);
                    mma_bf16(wa, wfh[kt][0], wfh[kt][1], wfh[kt][2], wfh[kt][3], bl0, bl1);
                }
                const int r0 = ntr * 8 + 2 * tg;
                const float sc0 = ssq[r0];
                const float sc1 = ssq[r0 + 1];
#pragma unroll
                for (int half = 0; half < 2; ++half) {
                    int m = w * 16 + gid + 8 * half;
                    float w0 = wa[2 * half], w1 = wa[2 * half + 1];
                    float e0 = (__expf(w0 - sc0) + EPSF) * SCALEF;
                    float e1 = (__expf(w1 - sc1) + EPSF) * SCALEF;
                    float g0 = (__expf(-w0 - sc0) + EPSF) * SCALEF;
                    float g1 = (__expf(-w1 - sc1) + EPSF) * SCALEF;
                    uint32_t he = pack_hi(e0, e1);
                    uint32_t hg = pack_hi(g0, g1);
                    *(uint32_t*)(smc + KA_H(buf) + m * 144 + r0 * 2)         = he;
                    *(uint32_t*)(smc + KA_L(buf) + m * 144 + r0 * 2)         = pack_lo(e0, e1, he);
                    *(uint32_t*)(smc + KA_H(buf) + (m + 128) * 144 + r0 * 2) = hg;
                    *(uint32_t*)(smc + KA_L(buf) + (m + 128) * 144 + r0 * 2) = pack_lo(g0, g1, hg);
                }
            }
            BAR_ARRIVE(1 + buf, 512);   /* A + BT ready for consumers */
        }
    } else {
        /* ============================ CONSUMER ============================ */
        const int cw = w - 8;               /* 0..7; features cw*32..+31 */
        const uint32_t bnc = (gid == 0) ? 0x3F803F80u : 0u;   /* ones column */

        float acc[2][8][4];
#pragma unroll
        for (int h = 0; h < 2; ++h)
#pragma unroll
            for (int nt = 0; nt < 8; ++nt)
#pragma unroll
                for (int p = 0; p < 4; ++p) acc[h][nt][p] = 0.f;
        float accN[2][4];
#pragma unroll
        for (int h = 0; h < 2; ++h)
#pragma unroll
            for (int p = 0; p < 4; ++p) accN[h][p] = 0.f;
        int seg = 0;

        for (int t = tb; t < te; ++t) {
            const int buf = t & 1;
            BAR_SYNC(1 + buf, 512);   /* wait A + BT */

            const uint32_t btB = sb + KBT(buf) + xq_lane;
            const uint32_t aH0 = sb + KA_H(buf) + (uint32_t)((cw * 32 + arow) * 144 + acolb);
            const uint32_t aH1 = aH0 + 16 * 144;
#pragma unroll
            for (int kt = 0; kt < 4; ++kt) {
                uint32_t ah[2][4], al[2][4];
                ldsm_x4(ah[0][0], ah[0][1], ah[0][2], ah[0][3], aH0 + kt * 32);
                ldsm_x4(al[0][0], al[0][1], al[0][2], al[0][3], aH0 + 36864 + kt * 32);
                ldsm_x4(ah[1][0], ah[1][1], ah[1][2], ah[1][3], aH1 + kt * 32);
                ldsm_x4(al[1][0], al[1][1], al[1][2], al[1][3], aH1 + 36864 + kt * 32);
#pragma unroll
                for (int nt = 0; nt < 8; ++nt) {
                    uint32_t bh0, bh1, bl0, bl1;
                    ldsm_x4(bh0, bh1, bl0, bl1, btB + nt * 2176 + kt * 32);
#pragma unroll
                    for (int h = 0; h < 2; ++h) {
                        mma_bf16(acc[h][nt], ah[h][0], ah[h][1], ah[h][2], ah[h][3], bh0, bh1);
                        mma_bf16(acc[h][nt], al[h][0], al[h][1], al[h][2], al[h][3], bh0, bh1);
                        mma_bf16(acc[h][nt], ah[h][0], ah[h][1], ah[h][2], ah[h][3], bl0, bl1);
                    }
                }
#pragma unroll
                for (int h = 0; h < 2; ++h) {
                    mma_bf16(accN[h], ah[h][0], ah[h][1], ah[h][2], ah[h][3], bnc, bnc);
                    mma_bf16(accN[h], al[h][0], al[h][1], al[h][2], al[h][3], bnc, bnc);
                }
            }
            BAR_ARRIVE(3 + buf, 512);   /* buf free for producers */

            if (t + 1 == te || ((t + 1) >> 7) != (t >> 7)) {
                float* base = &g_part[(size_t)(blk * 2 + seg) * TWOM * KVW];
#pragma unroll
                for (int h = 0; h < 2; ++h) {
                    const int f0 = cw * 32 + h * 16 + gid;
#pragma unroll
                    for (int nt = 0; nt < 8; ++nt) {
                        int c = nt * 8 + 2 * tg;
                        *(float2*)&base[f0 * KVW + c]       = make_float2(acc[h][nt][0], acc[h][nt][1]);
                        *(float2*)&base[(f0 + 8) * KVW + c] = make_float2(acc[h][nt][2], acc[h][nt][3]);
                    }
                    if (tg == 0) {
                        base[f0 * KVW + 64]       = accN[h][0];
                        base[(f0 + 8) * KVW + 64] = accN[h][2];
                    }
                }
                ++seg;
#pragma unroll
                for (int h = 0; h < 2; ++h) {
#pragma unroll
                    for (int nt = 0; nt < 8; ++nt)
#pragma unroll
                        for (int p = 0; p < 4; ++p) acc[h][nt][p] = 0.f;
#pragma unroll
                    for (int p = 0; p < 4; ++p) accN[h][p] = 0.f;
                }
            }
        }
    }
}

// ---------------------------------------------------------------------------
// Kernel 2: deterministic reduction (proven)
// ---------------------------------------------------------------------------
__global__ void reduce_kernel() {
    const int per_b4 = TWOM * KVW / 4;
    int idx = blockIdx.x * blockDim.x + threadIdx.x;
    int b = blockIdx.y;
    if (idx >= per_b4) return;
    float4 s = make_float4(0.f, 0.f, 0.f, 0.f);
    for (int i = 0; i < NBLK; ++i) {
        int tb = (i * NTILES) / NBLK;
        int te = ((i + 1) * NTILES) / NBLK;
        int b0 = tb >> 7;
        int bl = (te - 1) >> 7;
        int slot = (b0 == b) ? 0 : ((bl == b && bl != b0) ? 1 : -1);
        if (slot >= 0) {
            float4 v = ((const float4*)g_part)[(size_t)(i * 2 + slot) * per_b4 + idx];
            s.x += v.x; s.y += v.y; s.z += v.z; s.w += v.w;
        }
    }
    ((float4*)g_kv)[(size_t)b * per_b4 + idx] = s;
}

// ---------------------------------------------------------------------------
// Kernel 3 (round-13 proven): fully tensorized qkv with ldmatrix B fragments.
// ---------------------------------------------------------------------------
__global__ __launch_bounds__(512, 1)
void qkv_kernel(const float* __restrict__ query,
                const float* __restrict__ omega,
                float* __restrict__ out) {
    extern __shared__ char smc[];
    const uint32_t sb = smem_u32(smc);
    float* ssq_s  = (float*)(smc + QOFF_SQ);
    float* ns_s   = (float*)(smc + QOFF_NS);
    float* npb_s  = (float*)(smc + QOFF_NPB);
    uint32_t* BT  = (uint32_t*)(smc + QOFF_BT);

    const int tid = threadIdx.x;
    const int blk = blockIdx.x;
    const int tb = (blk * QTIL) / QNB;
    const int te = ((blk + 1) * QTIL) / QNB;

    {
        const float4* om4 = (const float4*)omega;
#pragma unroll
        for (int q = 0; q < 4; ++q) {
            int idx = tid + q * 512;
            float4 v = om4[idx];
            int m = idx >> 4, f = (idx & 15) * 4;
            uint32_t h01 = pack_hi(v.x, v.y), h23 = pack_hi(v.z, v.w);
            uint32_t* wh = (uint32_t*)(smc + QOFF_PH + m * 144 + f * 2);
            uint32_t* wl = (uint32_t*)(smc + QOFF_PL + m * 144 + f * 2);
            wh[0] = h01; wh[1] = h23;
            wl[0] = pack_lo(v.x, v.y, h01); wl[1] = pack_lo(v.z, v.w, h23);
        }
    }
    __syncthreads();

    const int w = tid >> 5, lane = tid & 31;
    const int gid = lane >> 2, tg = lane & 3;
    const int quad = lane >> 3, lrow = lane & 7;
    const int arow = lrow + (quad & 1) * 8;
    const int acolb = (quad >> 1) * 16;
    const int krow = lrow + (quad >> 1) * 8;
    const int mcol = (quad & 1) * 8;
    const int ldr = tid >> 4;
    const int mt = w >> 1;
    const int ntb = (w & 1) * 4;
    const int nt = w & 7, rh = w >> 3;
    const uint32_t xq_lane = (uint32_t)((lane & 7) * 272 + ((lane >> 3) & 1) * 16 + (lane >> 4) * 128);
    const uint32_t bq_lane = (uint32_t)((lane & 7) * 1040 + ((lane >> 3) & 1) * 16 + (lane >> 4) * 512);
    const uint32_t xtB = sb + QOFF_XT + xq_lane;
    const uint32_t btB = sb + QOFF_BT + bq_lane;

    uint32_t wfh[4][4], wfl[4][4];
    {
        uint32_t obase = sb + QOFF_PH + (uint32_t)((mt * 16 + arow) * 144 + acolb);
#pragma unroll
        for (int kt = 0; kt < 4; ++kt) {
            ldsm_x4(wfh[kt][0], wfh[kt][1], wfh[kt][2], wfh[kt][3], obase + kt * 32);
            ldsm_x4(wfl[kt][0], wfl[kt][1], wfl[kt][2], wfl[kt][3],
                    obase + (QOFF_PL - QOFF_PH) + kt * 32);
        }
    }

    int cur_b = -1;
    float4 px[4];
    {
        int t = tb, b = t >> 6, r0 = (t & 63) * 128;
        const float4* qp = (const float4*)(query + ((size_t)b * TT + r0) * FF);
#pragma unroll
        for (int q = 0; q < 4; ++q) px[q] = qp[tid + q * 512];
    }

    for (int t = tb; t < te; ++t) {
        const int b = t >> 6;
        const int r0 = (t & 63) * 128;

        if (b != cur_b) {
            const float* kvp = &g_kv[(size_t)b * TWOM * KVW];
            for (int i = tid; i < 128 * 64; i += 512) {
                int p = i >> 6, n = i & 63;
                float v0 = kvp[(2 * p) * KVW + n];
                float v1 = kvp[(2 * p + 1) * KVW + n];
                uint32_t hw = pack_hi(v0, v1);
                BT[n * 260 + p]       = hw;
                BT[n * 260 + 128 + p] = pack_lo(v0, v1, hw);
            }
            if (tid < 128) {
                int p = tid;
                float v0 = kvp[(2 * p) * KVW + 64];
                float v1 = kvp[(2 * p + 1) * KVW + 64];
                uint32_t hw = pack_hi(v0, v1);
                BT[64 * 260 + p]       = hw;
                BT[64 * 260 + 128 + p] = pack_lo(v0, v1, hw);
            }
            for (int i = tid; i < 7 * 256; i += 512) {
                int r = 65 + (i >> 8), wd = i & 255;
                BT[r * 260 + wd] = 0u;
            }
            cur_b = b;
        }

        for (int sub = 0; sub < 2; ++sub) {
#pragma unroll
            for (int q = 0; q < 2; ++q) {
                int r = ldr + q * 32;
                float4 xv = px[2 * sub + q];
                int p0 = (tid & 15) * 2;
                uint32_t h0 = pack_hi(xv.x, xv.y), h1 = pack_hi(xv.z, xv.w);
                uint32_t l0 = pack_lo(xv.x, xv.y, h0), l1 = pack_lo(xv.z, xv.w, h1);
                *(uint2*)(smc + QOFF_XT + (size_t)(r * 68 + p0) * 4)      = make_uint2(h0, h1);
                *(uint2*)(smc + QOFF_XT + (size_t)(r * 68 + 32 + p0) * 4) = make_uint2(l0, l1);
                float sq = xv.x * xv.x + xv.y * xv.y + xv.z * xv.z + xv.w * xv.w;
#pragma unroll
                for (int d = 1; d < 16; d <<= 1)
                    sq += __shfl_xor_sync(0xffffffffu, sq, d);
                if ((tid & 15) == 0) ssq_s[r] = 0.5f * sq;
            }
            if (sub == 1 && t + 1 < te) {
                int tn = t + 1, bn = tn >> 6, rn = (tn & 63) * 128;
                const float4* qp = (const float4*)(query + ((size_t)bn * TT + rn) * FF);
#pragma unroll
                for (int q = 0; q < 4; ++q) px[q] = qp[tid + q * 512];
            }
            __syncthreads();

#pragma unroll
            for (int nt4 = 0; nt4 < 4; ++nt4) {
                const int ntp = ntb + nt4;
                float wa[4] = {0.f, 0.f, 0.f, 0.f};
#pragma unroll
                for (int kt = 0; kt < 4; ++kt) {
                    uint32_t bh0, bh1, bl0, bl1;
                    ldsm_x4(bh0, bh1, bl0, bl1, xtB + ntp * 2176 + kt * 32);
                    mma_bf16(wa, wfh[kt][0], wfh[kt][1], wfh[kt][2], wfh[kt][3], bh0, bh1);
                    mma_bf16(wa, wfl[kt][0], wfl[kt][1], wfl[kt][2], wfl[kt][3], bh0, bh1);
                    mma_bf16(wa, wfh[kt][0], wfh[kt][1], wfh[kt][2], wfh[kt][3], bl0, bl1);
                }
                const int rr = ntp * 8 + 2 * tg;
                const float sc0 = ssq_s[rr];
                const float sc1 = ssq_s[rr + 1];
#pragma unroll
                for (int half = 0; half < 2; ++half) {
                    int m = mt * 16 + gid + 8 * half;
                    float w0 = wa[2 * half], w1 = wa[2 * half + 1];
                    float e0 = (__expf(w0 - sc0) + EPSF) * SCALEF;
                    float e1 = (__expf(w1 - sc1) + EPSF) * SCALEF;
                    float g0 = (__expf(-w0 - sc0) + EPSF) * SCALEF;
                    float g1 = (__expf(-w1 - sc1) + EPSF) * SCALEF;
                    uint32_t he = pack_hi(e0, e1);
                    uint32_t hg = pack_hi(g0, g1);
                    *(uint32_t*)(smc + QOFF_PH + m * 144 + rr * 2)         = he;
                    *(uint32_t*)(smc + QOFF_PL + m * 144 + rr * 2)         = pack_lo(e0, e1, he);
                    *(uint32_t*)(smc + QOFF_PH + (m + 128) * 144 + rr * 2) = hg;
                    *(uint32_t*)(smc + QOFF_PL + (m + 128) * 144 + rr * 2) = pack_lo(g0, g1, hg);
                }
            }
            __syncthreads();

            float acc[2][4];
            float accN[2][4];
#pragma unroll
            for (int rt = 0; rt < 2; ++rt)
#pragma unroll
                for (int p = 0; p < 4; ++p) { acc[rt][p] = 0.f; accN[rt][p] = 0.f; }

#pragma unroll
            for (int kt = 0; kt < 16; ++kt) {
                uint32_t bh0, bh1, bl0, bl1;
                ldsm_x4(bh0, bh1, bl0, bl1, btB + nt * 8320 + kt * 32);
                const bool isn = ((kt >> 1) == nt);
                uint32_t bn0 = 0, bn1 = 0, bm0 = 0, bm1 = 0;
                if (isn) ldsm_x4(bn0, bn1, bm0, bm1, btB + 64 * 1040 + kt * 32);
#pragma unroll
                for (int rt = 0; rt < 2; ++rt) {
                    const int rbase = rh * 32 + rt * 16;
                    uint32_t aaddr = sb + QOFF_PH +
                        (uint32_t)((kt * 16 + krow) * 144 + (rbase + mcol) * 2);
                    uint32_t laddr = aaddr + (QOFF_PL - QOFF_PH);
                    uint32_t a0, a1, a2, a3, l0, l1, l2, l3;
                    ldsm_x4_t(a0, a1, a2, a3, aaddr);
                    ldsm_x4_t(l0, l1, l2, l3, laddr);
                    mma_bf16(acc[rt], a0, a1, a2, a3, bh0, bh1);
                    mma_bf16(acc[rt], l0, l1, l2, l3, bh0, bh1);
                    mma_bf16(acc[rt], a0, a1, a2, a3, bl0, bl1);
                    if (isn) {
                        mma_bf16(accN[rt], a0, a1, a2, a3, bn0, bn1);
                        mma_bf16(accN[rt], l0, l1, l2, l3, bn0, bn1);
                        mma_bf16(accN[rt], a0, a1, a2, a3, bm0, bm1);
                    }
                }
            }
            if (tg == 0) {
#pragma unroll
                for (int rt = 0; rt < 2; ++rt) {
                    int rbase = rh * 32 + rt * 16;
                    npb_s[nt * 66 + rbase + gid]     = accN[rt][0];
                    npb_s[nt * 66 + rbase + gid + 8] = accN[rt][2];
                }
            }
            __syncthreads();
            if (tid < 64) {
                float s = 0.f;
#pragma unroll
                for (int j = 0; j < 8; ++j) s += npb_s[j * 66 + tid];
                ns_s[tid] = s;
            }
            __syncthreads();

#pragma unroll
            for (int rt = 0; rt < 2; ++rt) {
                int rbase = rh * 32 + rt * 16;
                int row0 = rbase + gid, row1 = row0 + 8;
                float inv0 = 1.0f / ns_s[row0];
                float inv1 = 1.0f / ns_s[row1];
                float* o0 = out + ((size_t)b * TT + r0 + sub * 64 + row0) * DD + nt * 8 + 2 * tg;
                float* o1 = out + ((size_t)b * TT + r0 + sub * 64 + row1) * DD + nt * 8 + 2 * tg;
                *(float2*)o0 = make_float2(acc[rt][0] * inv0, acc[rt][1] * inv0);
                *(float2*)o1 = make_float2(acc[rt][2] * inv1, acc[rt][3] * inv1);
            }
        }
    }
}

// ---------------------------------------------------------------------------

extern "C" void kernel_launch(void* const* d_in, const int* in_sizes, int n_in,
                              void* d_out, int out_size) {
    const float* query = (const float*)d_in[0];
    const float* value = (const float*)d_in[1];
    const float* key   = (const float*)d_in[2];
    const float* omega = (const float*)d_in[3];
    float* out = (float*)d_out;

    cudaFuncSetAttribute(kv_kernel, cudaFuncAttributeMaxDynamicSharedMemorySize, KV_SMEM);
    cudaFuncSetAttribute(qkv_kernel, cudaFuncAttributeMaxDynamicSharedMemorySize, QSMEM);

    kv_kernel<<<NBLK, 512, KV_SMEM>>>(key, value, omega);
    reduce_kernel<<<dim3((TWOM * KVW / 4 + 255) / 256, BB), 256>>>();
    qkv_kernel<<<QNB, 512, QSMEM>>>(query, omega, out);
}

// round 15
// speedup vs baseline: 1.0886x; 1.0886x over previous
#include <cuda_runtime.h>
#include <cuda_bf16.h>
#include <string.h>
#include <stdint.h>

#define BB 8
#define TT 8192
#define SN 8192
#define FF 64
#define DD 64
#define MMF 128
#define TWOM 256
#define EPSF 1e-9f
#define SCALEF 0.0625f   /* 1/sqrt(2*128) */
#define KVW 66           /* g_kv row stride: col 64 = normalizer, 65 pad */

#define NBLK 148
#define NTILES 1024      /* kv: 64-row tiles, 128 per batch */
#define QUNITS 1024      /* qkv: 64-row subtile units, 128 per batch */
#define QNB 148

__device__ float g_part[(size_t)NBLK * 2 * TWOM * KVW];
__device__ float g_kv[BB * TWOM * KVW];

static __device__ __forceinline__ uint32_t smem_u32(const void* p) {
    uint32_t a;
    asm("{ .reg .u64 t; cvta.to.shared.u64 t, %1; cvt.u32.u64 %0, t; }" : "=r"(a) : "l"(p));
    return a;
}
static __device__ __forceinline__ void ldsm_x4(uint32_t& r0, uint32_t& r1,
                                               uint32_t& r2, uint32_t& r3, uint32_t addr) {
    asm volatile("ldmatrix.sync.aligned.m8n8.x4.shared.b16 {%0,%1,%2,%3}, [%4];"
                 : "=r"(r0), "=r"(r1), "=r"(r2), "=r"(r3) : "r"(addr));
}
static __device__ __forceinline__ void ldsm_x4_t(uint32_t& r0, uint32_t& r1,
                                                 uint32_t& r2, uint32_t& r3, uint32_t addr) {
    asm volatile("ldmatrix.sync.aligned.m8n8.x4.trans.shared.b16 {%0,%1,%2,%3}, [%4];"
                 : "=r"(r0), "=r"(r1), "=r"(r2), "=r"(r3) : "r"(addr));
}
static __device__ __forceinline__ void mma_bf16(float* c,
                                                uint32_t a0, uint32_t a1, uint32_t a2, uint32_t a3,
                                                uint32_t b0, uint32_t b1) {
    asm volatile("mma.sync.aligned.m16n8k16.row.col.f32.bf16.bf16.f32 "
                 "{%0,%1,%2,%3}, {%4,%5,%6,%7}, {%8,%9}, {%0,%1,%2,%3};"
                 : "+f"(c[0]), "+f"(c[1]), "+f"(c[2]), "+f"(c[3])
                 : "r"(a0), "r"(a1), "r"(a2), "r"(a3), "r"(b0), "r"(b1));
}
static __device__ __forceinline__ uint32_t pack_hi(float e0, float e1) {
    __nv_bfloat162 hp;
    hp.x = __float2bfloat16_rn(e0); hp.y = __float2bfloat16_rn(e1);
    uint32_t u; memcpy(&u, &hp, 4); return u;
}
static __device__ __forceinline__ uint32_t pack_lo(float e0, float e1, uint32_t hi) {
    __nv_bfloat162 hp; memcpy(&hp, &hi, 4);
    __nv_bfloat162 lp;
    lp.x = __float2bfloat16_rn(e0 - __bfloat162float(hp.x));
    lp.y = __float2bfloat16_rn(e1 - __bfloat162float(hp.y));
    uint32_t u; memcpy(&u, &lp, 4); return u;
}

/* ---------- kv smem (round-13 proven) ---------- */
#define KOFF_AH 0
#define KOFF_AL 36864
#define KOFF_V  73728
#define KOFF_XT 91136
#define KOFF_BT 108544
#define KOFF_SQ 125952
#define KV_SMEM 126208

/* ---------- qkv smem (round-13 proven) ---------- */
#define QOFF_PH 0
#define QOFF_PL 36864
#define QOFF_BT 73728      /* kv BT [72][260w] */
#define QOFF_XT 148608     /* x BT [64][68w] */
#define QOFF_SQ 166016
#define QOFF_NS 166272
#define QOFF_NPB 166528
#define QSMEM   168640

// ---------------------------------------------------------------------------
// Kernel 1 (round-13 proven): fully tensorized kv, ldmatrix B fragments.
// ---------------------------------------------------------------------------
__global__ __launch_bounds__(512, 1)
void kv_kernel(const float* __restrict__ key,
               const float* __restrict__ value,
               const float* __restrict__ omega) {
    extern __shared__ char smc[];
    const uint32_t sb = smem_u32(smc);
    float* v_s    = (float*)(smc + KOFF_V);
    float* ssq_s  = (float*)(smc + KOFF_SQ);
    uint32_t* BT  = (uint32_t*)(smc + KOFF_BT);

    const int tid = threadIdx.x;
    const int blk = blockIdx.x;
    const int tb = (blk * NTILES) / NBLK;
    const int te = ((blk + 1) * NTILES) / NBLK;

    {
        const float4* om4 = (const float4*)omega;
#pragma unroll
        for (int q = 0; q < 4; ++q) {
            int idx = tid + q * 512;
            float4 v = om4[idx];
            int m = idx >> 4, f = (idx & 15) * 4;
            uint32_t h01 = pack_hi(v.x, v.y), h23 = pack_hi(v.z, v.w);
            uint32_t* wh = (uint32_t*)(smc + KOFF_AH + m * 144 + f * 2);
            uint32_t* wl = (uint32_t*)(smc + KOFF_AL + m * 144 + f * 2);
            wh[0] = h01; wh[1] = h23;
            wl[0] = pack_lo(v.x, v.y, h01); wl[1] = pack_lo(v.z, v.w, h23);
        }
    }
    __syncthreads();

    const int w = tid >> 5, lane = tid & 31;
    const int gid = lane >> 2, tg = lane & 3;
    const int quad = lane >> 3, lrow = lane & 7;
    const int arow = lrow + (quad & 1) * 8;
    const int acolb = (quad >> 1) * 16;
    const int ldr = tid >> 4;
    const int ldc = (tid & 15) * 4;
    const int mt = w >> 1;
    const int ntb = (w & 1) * 4;
    const uint32_t aBase = sb + KOFF_AH + (uint32_t)((w * 16 + arow) * 144 + acolb);
    const uint32_t xq_lane = (uint32_t)((lane & 7) * 272 + ((lane >> 3) & 1) * 16 + (lane >> 4) * 128);
    const uint32_t xtB = sb + KOFF_XT + xq_lane;
    const uint32_t btB = sb + KOFF_BT + xq_lane;
    const uint32_t bnc = (gid == 0) ? 0x3F803F80u : 0u;

    uint32_t wfh[4][4], wfl[4][4];
    {
        uint32_t obase = sb + KOFF_AH + (uint32_t)((mt * 16 + arow) * 144 + acolb);
#pragma unroll
        for (int kt = 0; kt < 4; ++kt) {
            ldsm_x4(wfh[kt][0], wfh[kt][1], wfh[kt][2], wfh[kt][3], obase + kt * 32);
            ldsm_x4(wfl[kt][0], wfl[kt][1], wfl[kt][2], wfl[kt][3],
                    obase + (KOFF_AL - KOFF_AH) + kt * 32);
        }
    }

    float acc[8][4];
#pragma unroll
    for (int nt = 0; nt < 8; ++nt)
#pragma unroll
        for (int p = 0; p < 4; ++p) acc[nt][p] = 0.f;
    float accN[4] = {0.f, 0.f, 0.f, 0.f};
    int seg = 0;

    float4 px[2], pv[2];
    {
        int t = tb, b = t >> 7, s0 = (t & 127) * 64;
        const float4* kp = (const float4*)(key   + ((size_t)b * SN + s0) * FF);
        const float4* vp = (const float4*)(value + ((size_t)b * SN + s0) * FF);
#pragma unroll
        for (int q = 0; q < 2; ++q) { px[q] = kp[tid + q * 512]; pv[q] = vp[tid + q * 512]; }
    }

    for (int t = tb; t < te; ++t) {
        /* no barrier: stage buffers' last readers precede prev A-ready barrier */
#pragma unroll
        for (int q = 0; q < 2; ++q) {
            int r = ldr + q * 32;
            float4 xv = px[q];
            int p0 = (tid & 15) * 2;
            uint32_t h0 = pack_hi(xv.x, xv.y), h1 = pack_hi(xv.z, xv.w);
            uint32_t l0 = pack_lo(xv.x, xv.y, h0), l1 = pack_lo(xv.z, xv.w, h1);
            *(uint2*)(smc + KOFF_XT + (size_t)(r * 68 + p0) * 4)      = make_uint2(h0, h1);
            *(uint2*)(smc + KOFF_XT + (size_t)(r * 68 + 32 + p0) * 4) = make_uint2(l0, l1);
            *(float4*)&v_s[r * 68 + ldc] = pv[q];
            float sq = xv.x * xv.x + xv.y * xv.y + xv.z * xv.z + xv.w * xv.w;
#pragma unroll
            for (int d = 1; d < 16; d <<= 1)
                sq += __shfl_xor_sync(0xffffffffu, sq, d);
            if ((tid & 15) == 0) ssq_s[r] = 0.5f * sq;
        }
        if (t + 1 < te) {
            int tn = t + 1, b = tn >> 7, s0 = (tn & 127) * 64;
            const float4* kp = (const float4*)(key   + ((size_t)b * SN + s0) * FF);
            const float4* vp = (const float4*)(value + ((size_t)b * SN + s0) * FF);
#pragma unroll
            for (int q = 0; q < 2; ++q) { px[q] = kp[tid + q * 512]; pv[q] = vp[tid + q * 512]; }
        }
        __syncthreads();   /* XT, v, ssq ready; prev kv-MMA complete */

#pragma unroll
        for (int q = 0; q < 4; ++q) {
            int idx = tid + q * 512;
            int p = idx >> 6, n = idx & 63;
            float v0 = v_s[(2 * p) * 68 + n];
            float v1 = v_s[(2 * p + 1) * 68 + n];
            uint32_t hw = pack_hi(v0, v1);
            BT[n * 68 + p]      = hw;
            BT[n * 68 + 32 + p] = pack_lo(v0, v1, hw);
        }

#pragma unroll
        for (int nt4 = 0; nt4 < 4; ++nt4) {
            const int nt = ntb + nt4;
            float wa[4] = {0.f, 0.f, 0.f, 0.f};
#pragma unroll
            for (int kt = 0; kt < 4; ++kt) {
                uint32_t bh0, bh1, bl0, bl1;
                ldsm_x4(bh0, bh1, bl0, bl1, xtB + nt * 2176 + kt * 32);
                mma_bf16(wa, wfh[kt][0], wfh[kt][1], wfh[kt][2], wfh[kt][3], bh0, bh1);
                mma_bf16(wa, wfl[kt][0], wfl[kt][1], wfl[kt][2], wfl[kt][3], bh0, bh1);
                mma_bf16(wa, wfh[kt][0], wfh[kt][1], wfh[kt][2], wfh[kt][3], bl0, bl1);
            }
            const int r0 = nt * 8 + 2 * tg;
            const float sc0 = ssq_s[r0];
            const float sc1 = ssq_s[r0 + 1];
#pragma unroll
            for (int half = 0; half < 2; ++half) {
                int m = mt * 16 + gid + 8 * half;
                float w0 = wa[2 * half], w1 = wa[2 * half + 1];
                float e0 = (__expf(w0 - sc0) + EPSF) * SCALEF;
                float e1 = (__expf(w1 - sc1) + EPSF) * SCALEF;
                float g0 = (__expf(-w0 - sc0) + EPSF) * SCALEF;
                float g1 = (__expf(-w1 - sc1) + EPSF) * SCALEF;
                uint32_t he = pack_hi(e0, e1);
                uint32_t hg = pack_hi(g0, g1);
                *(uint32_t*)(smc + KOFF_AH + m * 144 + r0 * 2)         = he;
                *(uint32_t*)(smc + KOFF_AL + m * 144 + r0 * 2)         = pack_lo(e0, e1, he);
                *(uint32_t*)(smc + KOFF_AH + (m + 128) * 144 + r0 * 2) = hg;
                *(uint32_t*)(smc + KOFF_AL + (m + 128) * 144 + r0 * 2) = pack_lo(g0, g1, hg);
            }
        }
        __syncthreads();   /* A_phi, BT ready */

#pragma unroll
        for (int kt = 0; kt < 4; ++kt) {
            uint32_t ah0, ah1, ah2, ah3, al0, al1, al2, al3;
            ldsm_x4(ah0, ah1, ah2, ah3, aBase + kt * 32);
            ldsm_x4(al0, al1, al2, al3, aBase + (KOFF_AL - KOFF_AH) + kt * 32);
#pragma unroll
            for (int nt = 0; nt < 8; ++nt) {
                uint32_t bh0, bh1, bl0, bl1;
                ldsm_x4(bh0, bh1, bl0, bl1, btB + nt * 2176 + kt * 32);
                mma_bf16(acc[nt], ah0, ah1, ah2, ah3, bh0, bh1);
                mma_bf16(acc[nt], al0, al1, al2, al3, bh0, bh1);
                mma_bf16(acc[nt], ah0, ah1, ah2, ah3, bl0, bl1);
            }
            mma_bf16(accN, ah0, ah1, ah2, ah3, bnc, bnc);
            mma_bf16(accN, al0, al1, al2, al3, bnc, bnc);
        }

        if (t + 1 == te || ((t + 1) >> 7) != (t >> 7)) {
            float* base = &g_part[(size_t)(blk * 2 + seg) * TWOM * KVW];
            const int f0 = w * 16 + gid;
#pragma unroll
            for (int nt = 0; nt < 8; ++nt) {
                int c = nt * 8 + 2 * tg;
                *(float2*)&base[f0 * KVW + c]       = make_float2(acc[nt][0], acc[nt][1]);
                *(float2*)&base[(f0 + 8) * KVW + c] = make_float2(acc[nt][2], acc[nt][3]);
            }
            if (tg == 0) {
                base[f0 * KVW + 64]       = accN[0];
                base[(f0 + 8) * KVW + 64] = accN[2];
            }
            ++seg;
#pragma unroll
            for (int nt = 0; nt < 8; ++nt)
#pragma unroll
                for (int p = 0; p < 4; ++p) acc[nt][p] = 0.f;
#pragma unroll
            for (int p = 0; p < 4; ++p) accN[p] = 0.f;
        }
    }
}

// ---------------------------------------------------------------------------
// Kernel 2: deterministic reduction (proven)
// ---------------------------------------------------------------------------
__global__ void reduce_kernel() {
    const int per_b4 = TWOM * KVW / 4;
    int idx = blockIdx.x * blockDim.x + threadIdx.x;
    int b = blockIdx.y;
    if (idx >= per_b4) return;
    float4 s = make_float4(0.f, 0.f, 0.f, 0.f);
    for (int i = 0; i < NBLK; ++i) {
        int tb = (i * NTILES) / NBLK;
        int te = ((i + 1) * NTILES) / NBLK;
        int b0 = tb >> 7;
        int bl = (te - 1) >> 7;
        int slot = (b0 == b) ? 0 : ((bl == b && bl != b0) ? 1 : -1);
        if (slot >= 0) {
            float4 v = ((const float4*)g_part)[(size_t)(i * 2 + slot) * per_b4 + idx];
            s.x += v.x; s.y += v.y; s.z += v.z; s.w += v.w;
        }
    }
    ((float4*)g_kv)[(size_t)b * per_b4 + idx] = s;
}

// ---------------------------------------------------------------------------
// Kernel 3: round-13 qkv rescheduled on 64-row subtile units (1024 over 148
// blocks, te-tb in {6,7}) — kills the 128-row-tile wave quantization.
// All layouts/mappings/barriers identical to round-13.
// ---------------------------------------------------------------------------
__global__ __launch_bounds__(512, 1)
void qkv_kernel(const float* __restrict__ query,
                const float* __restrict__ omega,
                float* __restrict__ out) {
    extern __shared__ char smc[];
    const uint32_t sb = smem_u32(smc);
    float* ssq_s  = (float*)(smc + QOFF_SQ);
    float* ns_s   = (float*)(smc + QOFF_NS);
    float* npb_s  = (float*)(smc + QOFF_NPB);
    uint32_t* BT  = (uint32_t*)(smc + QOFF_BT);

    const int tid = threadIdx.x;
    const int blk = blockIdx.x;
    const int tb = (blk * QUNITS) / QNB;
    const int te = ((blk + 1) * QUNITS) / QNB;

    {
        const float4* om4 = (const float4*)omega;
#pragma unroll
        for (int q = 0; q < 4; ++q) {
            int idx = tid + q * 512;
            float4 v = om4[idx];
            int m = idx >> 4, f = (idx & 15) * 4;
            uint32_t h01 = pack_hi(v.x, v.y), h23 = pack_hi(v.z, v.w);
            uint32_t* wh = (uint32_t*)(smc + QOFF_PH + m * 144 + f * 2);
            uint32_t* wl = (uint32_t*)(smc + QOFF_PL + m * 144 + f * 2);
            wh[0] = h01; wh[1] = h23;
            wl[0] = pack_lo(v.x, v.y, h01); wl[1] = pack_lo(v.z, v.w, h23);
        }
    }
    __syncthreads();

    const int w = tid >> 5, lane = tid & 31;
    const int gid = lane >> 2, tg = lane & 3;
    const int quad = lane >> 3, lrow = lane & 7;
    const int arow = lrow + (quad & 1) * 8;
    const int acolb = (quad >> 1) * 16;
    const int krow = lrow + (quad >> 1) * 8;
    const int mcol = (quad & 1) * 8;
    const int ldr = tid >> 4;
    const int mt = w >> 1;
    const int ntb = (w & 1) * 4;
    const int nt = w & 7, rh = w >> 3;
    const uint32_t xq_lane = (uint32_t)((lane & 7) * 272 + ((lane >> 3) & 1) * 16 + (lane >> 4) * 128);
    const uint32_t bq_lane = (uint32_t)((lane & 7) * 1040 + ((lane >> 3) & 1) * 16 + (lane >> 4) * 512);
    const uint32_t xtB = sb + QOFF_XT + xq_lane;
    const uint32_t btB = sb + QOFF_BT + bq_lane;

    uint32_t wfh[4][4], wfl[4][4];
    {
        uint32_t obase = sb + QOFF_PH + (uint32_t)((mt * 16 + arow) * 144 + acolb);
#pragma unroll
        for (int kt = 0; kt < 4; ++kt) {
            ldsm_x4(wfh[kt][0], wfh[kt][1], wfh[kt][2], wfh[kt][3], obase + kt * 32);
            ldsm_x4(wfl[kt][0], wfl[kt][1], wfl[kt][2], wfl[kt][3],
                    obase + (QOFF_PL - QOFF_PH) + kt * 32);
        }
    }

    int cur_b = -1;
    float4 px[2];
    {
        int t = tb, b = t >> 7, r0 = (t & 127) * 64;
        const float4* qp = (const float4*)(query + ((size_t)b * TT + r0) * FF);
#pragma unroll
        for (int q = 0; q < 2; ++q) px[q] = qp[tid + q * 512];
    }

    for (int t = tb; t < te; ++t) {
        const int b = t >> 7;
        const int r0 = (t & 127) * 64;

        if (b != cur_b) {
            /* BT rebuild; prior qkv-MMA reads precede prev partials barrier */
            const float* kvp = &g_kv[(size_t)b * TWOM * KVW];
            for (int i = tid; i < 128 * 64; i += 512) {
                int p = i >> 6, n = i & 63;
                float v0 = kvp[(2 * p) * KVW + n];
                float v1 = kvp[(2 * p + 1) * KVW + n];
                uint32_t hw = pack_hi(v0, v1);
                BT[n * 260 + p]       = hw;
                BT[n * 260 + 128 + p] = pack_lo(v0, v1, hw);
            }
            if (tid < 128) {
                int p = tid;
                float v0 = kvp[(2 * p) * KVW + 64];
                float v1 = kvp[(2 * p + 1) * KVW + 64];
                uint32_t hw = pack_hi(v0, v1);
                BT[64 * 260 + p]       = hw;
                BT[64 * 260 + 128 + p] = pack_lo(v0, v1, hw);
            }
            for (int i = tid; i < 7 * 256; i += 512) {
                int r = 65 + (i >> 8), wd = i & 255;
                BT[r * 260 + wd] = 0u;
            }
            cur_b = b;
        }

        /* stage x -> XT hi/lo + ssq (no top barrier; audited) */
#pragma unroll
        for (int q = 0; q < 2; ++q) {
            int r = ldr + q * 32;
            float4 xv = px[q];
            int p0 = (tid & 15) * 2;
            uint32_t h0 = pack_hi(xv.x, xv.y), h1 = pack_hi(xv.z, xv.w);
            uint32_t l0 = pack_lo(xv.x, xv.y, h0), l1 = pack_lo(xv.z, xv.w, h1);
            *(uint2*)(smc + QOFF_XT + (size_t)(r * 68 + p0) * 4)      = make_uint2(h0, h1);
            *(uint2*)(smc + QOFF_XT + (size_t)(r * 68 + 32 + p0) * 4) = make_uint2(l0, l1);
            float sq = xv.x * xv.x + xv.y * xv.y + xv.z * xv.z + xv.w * xv.w;
#pragma unroll
            for (int d = 1; d < 16; d <<= 1)
                sq += __shfl_xor_sync(0xffffffffu, sq, d);
            if ((tid & 15) == 0) ssq_s[r] = 0.5f * sq;
        }
        if (t + 1 < te) {
            int tn = t + 1, bn = tn >> 7, rn = (tn & 127) * 64;
            const float4* qp = (const float4*)(query + ((size_t)bn * TT + rn) * FF);
#pragma unroll
            for (int q = 0; q < 2; ++q) px[q] = qp[tid + q * 512];
        }
        __syncthreads();   /* XT, ssq (and BT after rebuild) ready */

        /* phi-MMA + exp + phiT store */
#pragma unroll
        for (int nt4 = 0; nt4 < 4; ++nt4) {
            const int ntp = ntb + nt4;
            float wa[4] = {0.f, 0.f, 0.f, 0.f};
#pragma unroll
            for (int kt = 0; kt < 4; ++kt) {
                uint32_t bh0, bh1, bl0, bl1;
                ldsm_x4(bh0, bh1, bl0, bl1, xtB + ntp * 2176 + kt * 32);
                mma_bf16(wa, wfh[kt][0], wfh[kt][1], wfh[kt][2], wfh[kt][3], bh0, bh1);
                mma_bf16(wa, wfl[kt][0], wfl[kt][1], wfl[kt][2], wfl[kt][3], bh0, bh1);
                mma_bf16(wa, wfh[kt][0], wfh[kt][1], wfh[kt][2], wfh[kt][3], bl0, bl1);
            }
            const int rr = ntp * 8 + 2 * tg;
            const float sc0 = ssq_s[rr];
            const float sc1 = ssq_s[rr + 1];
#pragma unroll
            for (int half = 0; half < 2; ++half) {
                int m = mt * 16 + gid + 8 * half;
                float w0 = wa[2 * half], w1 = wa[2 * half + 1];
                float e0 = (__expf(w0 - sc0) + EPSF) * SCALEF;
                float e1 = (__expf(w1 - sc1) + EPSF) * SCALEF;
                float g0 = (__expf(-w0 - sc0) + EPSF) * SCALEF;
                float g1 = (__expf(-w1 - sc1) + EPSF) * SCALEF;
                uint32_t he = pack_hi(e0, e1);
                uint32_t hg = pack_hi(g0, g1);
                *(uint32_t*)(smc + QOFF_PH + m * 144 + rr * 2)         = he;
                *(uint32_t*)(smc + QOFF_PL + m * 144 + rr * 2)         = pack_lo(e0, e1, he);
                *(uint32_t*)(smc + QOFF_PH + (m + 128) * 144 + rr * 2) = hg;
                *(uint32_t*)(smc + QOFF_PL + (m + 128) * 144 + rr * 2) = pack_lo(g0, g1, hg);
            }
        }
        __syncthreads();   /* phiT ready */

        /* qkv-MMA; balanced full 3-term norm on kt = 2nt, 2nt+1 */
        float acc[2][4];
        float accN[2][4];
#pragma unroll
        for (int rt = 0; rt < 2; ++rt)
#pragma unroll
            for (int p = 0; p < 4; ++p) { acc[rt][p] = 0.f; accN[rt][p] = 0.f; }

#pragma unroll
        for (int kt = 0; kt < 16; ++kt) {
            uint32_t bh0, bh1, bl0, bl1;
            ldsm_x4(bh0, bh1, bl0, bl1, btB + nt * 8320 + kt * 32);
            const bool isn = ((kt >> 1) == nt);
            uint32_t bn0 = 0, bn1 = 0, bm0 = 0, bm1 = 0;
            if (isn) ldsm_x4(bn0, bn1, bm0, bm1, btB + 64 * 1040 + kt * 32);
#pragma unroll
            for (int rt = 0; rt < 2; ++rt) {
                const int rbase = rh * 32 + rt * 16;
                uint32_t aaddr = sb + QOFF_PH +
                    (uint32_t)((kt * 16 + krow) * 144 + (rbase + mcol) * 2);
                uint32_t laddr = aaddr + (QOFF_PL - QOFF_PH);
                uint32_t a0, a1, a2, a3, l0, l1, l2, l3;
                ldsm_x4_t(a0, a1, a2, a3, aaddr);
                ldsm_x4_t(l0, l1, l2, l3, laddr);
                mma_bf16(acc[rt], a0, a1, a2, a3, bh0, bh1);
                mma_bf16(acc[rt], l0, l1, l2, l3, bh0, bh1);
                mma_bf16(acc[rt], a0, a1, a2, a3, bl0, bl1);
                if (isn) {
                    mma_bf16(accN[rt], a0, a1, a2, a3, bn0, bn1);
                    mma_bf16(accN[rt], l0, l1, l2, l3, bn0, bn1);
                    mma_bf16(accN[rt], a0, a1, a2, a3, bm0, bm1);
                }
            }
        }
        if (tg == 0) {
#pragma unroll
            for (int rt = 0; rt < 2; ++rt) {
                int rbase = rh * 32 + rt * 16;
                npb_s[nt * 66 + rbase + gid]     = accN[rt][0];
                npb_s[nt * 66 + rbase + gid + 8] = accN[rt][2];
            }
        }
        __syncthreads();   /* partials ready */
        if (tid < 64) {
            float s = 0.f;
#pragma unroll
            for (int j = 0; j < 8; ++j) s += npb_s[j * 66 + tid];
            ns_s[tid] = s;
        }
        __syncthreads();   /* norm ready */

        /* epilogue */
#pragma unroll
        for (int rt = 0; rt < 2; ++rt) {
            int rbase = rh * 32 + rt * 16;
            int row0 = rbase + gid, row1 = row0 + 8;
            float inv0 = 1.0f / ns_s[row0];
            float inv1 = 1.0f / ns_s[row1];
            float* o0 = out + ((size_t)b * TT + r0 + row0) * DD + nt * 8 + 2 * tg;
            float* o1 = out + ((size_t)b * TT + r0 + row1) * DD + nt * 8 + 2 * tg;
            *(float2*)o0 = make_float2(acc[rt][0] * inv0, acc[rt][1] * inv0);
            *(float2*)o1 = make_float2(acc[rt][2] * inv1, acc[rt][3] * inv1);
        }
    }
}

// ---------------------------------------------------------------------------

extern "C" void kernel_launch(void* const* d_in, const int* in_sizes, int n_in,
                              void* d_out, int out_size) {
    const float* query = (const float*)d_in[0];
    const float* value = (const float*)d_in[1];
    const float* key   = (const float*)d_in[2];
    const float* omega = (const float*)d_in[3];
    float* out = (float*)d_out;

    cudaFuncSetAttribute(kv_kernel, cudaFuncAttributeMaxDynamicSharedMemorySize, KV_SMEM);
    cudaFuncSetAttribute(qkv_kernel, cudaFuncAttributeMaxDynamicSharedMemorySize, QSMEM);

    kv_kernel<<<NBLK, 512, KV_SMEM>>>(key, value, omega);
    reduce_kernel<<<dim3((TWOM * KVW / 4 + 255) / 256, BB), 256>>>();
    qkv_kernel<<<QNB, 512, QSMEM>>>(query, omega, out);
}

// round 16
// speedup vs baseline: 1.2066x; 1.1084x over previous
#include <cuda_runtime.h>
#include <cuda_bf16.h>
#include <string.h>
#include <stdint.h>

#define BB 8
#define TT 8192
#define SN 8192
#define FF 64
#define DD 64
#define MMF 128
#define TWOM 256
#define EPSF 1e-9f
#define SCALEF 0.0625f   /* 1/sqrt(2*128) */
#define KVW 66           /* g_kv row stride: col 64 = normalizer, 65 pad */

#define NBLK 148
#define NTILES 1024      /* kv: 64-row tiles, 128 per batch */
#define QUNITS 1024      /* qkv: 64-row subtile units, 128 per batch */
#define QNB 148

__device__ float g_part[(size_t)NBLK * 2 * TWOM * KVW];
__device__ float g_kv[BB * TWOM * KVW];

static __device__ __forceinline__ uint32_t smem_u32(const void* p) {
    uint32_t a;
    asm("{ .reg .u64 t; cvta.to.shared.u64 t, %1; cvt.u32.u64 %0, t; }" : "=r"(a) : "l"(p));
    return a;
}
static __device__ __forceinline__ void ldsm_x4(uint32_t& r0, uint32_t& r1,
                                               uint32_t& r2, uint32_t& r3, uint32_t addr) {
    asm volatile("ldmatrix.sync.aligned.m8n8.x4.shared.b16 {%0,%1,%2,%3}, [%4];"
                 : "=r"(r0), "=r"(r1), "=r"(r2), "=r"(r3) : "r"(addr));
}
static __device__ __forceinline__ void ldsm_x4_t(uint32_t& r0, uint32_t& r1,
                                                 uint32_t& r2, uint32_t& r3, uint32_t addr) {
    asm volatile("ldmatrix.sync.aligned.m8n8.x4.trans.shared.b16 {%0,%1,%2,%3}, [%4];"
                 : "=r"(r0), "=r"(r1), "=r"(r2), "=r"(r3) : "r"(addr));
}
static __device__ __forceinline__ void mma_bf16(float* c,
                                                uint32_t a0, uint32_t a1, uint32_t a2, uint32_t a3,
                                                uint32_t b0, uint32_t b1) {
    asm volatile("mma.sync.aligned.m16n8k16.row.col.f32.bf16.bf16.f32 "
                 "{%0,%1,%2,%3}, {%4,%5,%6,%7}, {%8,%9}, {%0,%1,%2,%3};"
                 : "+f"(c[0]), "+f"(c[1]), "+f"(c[2]), "+f"(c[3])
                 : "r"(a0), "r"(a1), "r"(a2), "r"(a3), "r"(b0), "r"(b1));
}
static __device__ __forceinline__ uint32_t pack_hi(float e0, float e1) {
    __nv_bfloat162 hp;
    hp.x = __float2bfloat16_rn(e0); hp.y = __float2bfloat16_rn(e1);
    uint32_t u; memcpy(&u, &hp, 4); return u;
}
static __device__ __forceinline__ uint32_t pack_lo(float e0, float e1, uint32_t hi) {
    __nv_bfloat162 hp; memcpy(&hp, &hi, 4);
    __nv_bfloat162 lp;
    lp.x = __float2bfloat16_rn(e0 - __bfloat162float(hp.x));
    lp.y = __float2bfloat16_rn(e1 - __bfloat162float(hp.y));
    uint32_t u; memcpy(&u, &lp, 4); return u;
}

/* ---------- kv smem (round-13 proven) ---------- */
#define KOFF_AH 0
#define KOFF_AL 36864
#define KOFF_V  73728
#define KOFF_XT 91136
#define KOFF_BT 108544
#define KOFF_SQ 125952
#define KV_SMEM 126208

/* ---------- qkv smem (round-13 proven) ---------- */
#define QOFF_PH 0
#define QOFF_PL 36864
#define QOFF_BT 73728      /* kv BT [72][260w] */
#define QOFF_XT 148608     /* x BT [64][68w] */
#define QOFF_SQ 166016
#define QOFF_NS 166272
#define QOFF_NPB 166528    /* norm partials [4][66] */
#define QSMEM   168640

// ---------------------------------------------------------------------------
// Kernel 1 (round-13 proven): fully tensorized kv, ldmatrix B fragments.
// ---------------------------------------------------------------------------
__global__ __launch_bounds__(512, 1)
void kv_kernel(const float* __restrict__ key,
               const float* __restrict__ value,
               const float* __restrict__ omega) {
    extern __shared__ char smc[];
    const uint32_t sb = smem_u32(smc);
    float* v_s    = (float*)(smc + KOFF_V);
    float* ssq_s  = (float*)(smc + KOFF_SQ);
    uint32_t* BT  = (uint32_t*)(smc + KOFF_BT);

    const int tid = threadIdx.x;
    const int blk = blockIdx.x;
    const int tb = (blk * NTILES) / NBLK;
    const int te = ((blk + 1) * NTILES) / NBLK;

    {
        const float4* om4 = (const float4*)omega;
#pragma unroll
        for (int q = 0; q < 4; ++q) {
            int idx = tid + q * 512;
            float4 v = om4[idx];
            int m = idx >> 4, f = (idx & 15) * 4;
            uint32_t h01 = pack_hi(v.x, v.y), h23 = pack_hi(v.z, v.w);
            uint32_t* wh = (uint32_t*)(smc + KOFF_AH + m * 144 + f * 2);
            uint32_t* wl = (uint32_t*)(smc + KOFF_AL + m * 144 + f * 2);
            wh[0] = h01; wh[1] = h23;
            wl[0] = pack_lo(v.x, v.y, h01); wl[1] = pack_lo(v.z, v.w, h23);
        }
    }
    __syncthreads();

    const int w = tid >> 5, lane = tid & 31;
    const int gid = lane >> 2, tg = lane & 3;
    const int quad = lane >> 3, lrow = lane & 7;
    const int arow = lrow + (quad & 1) * 8;
    const int acolb = (quad >> 1) * 16;
    const int ldr = tid >> 4;
    const int ldc = (tid & 15) * 4;
    const int mt = w >> 1;
    const int ntb = (w & 1) * 4;
    const uint32_t aBase = sb + KOFF_AH + (uint32_t)((w * 16 + arow) * 144 + acolb);
    const uint32_t xq_lane = (uint32_t)((lane & 7) * 272 + ((lane >> 3) & 1) * 16 + (lane >> 4) * 128);
    const uint32_t xtB = sb + KOFF_XT + xq_lane;
    const uint32_t btB = sb + KOFF_BT + xq_lane;
    const uint32_t bnc = (gid == 0) ? 0x3F803F80u : 0u;

    uint32_t wfh[4][4], wfl[4][4];
    {
        uint32_t obase = sb + KOFF_AH + (uint32_t)((mt * 16 + arow) * 144 + acolb);
#pragma unroll
        for (int kt = 0; kt < 4; ++kt) {
            ldsm_x4(wfh[kt][0], wfh[kt][1], wfh[kt][2], wfh[kt][3], obase + kt * 32);
            ldsm_x4(wfl[kt][0], wfl[kt][1], wfl[kt][2], wfl[kt][3],
                    obase + (KOFF_AL - KOFF_AH) + kt * 32);
        }
    }

    float acc[8][4];
#pragma unroll
    for (int nt = 0; nt < 8; ++nt)
#pragma unroll
        for (int p = 0; p < 4; ++p) acc[nt][p] = 0.f;
    float accN[4] = {0.f, 0.f, 0.f, 0.f};
    int seg = 0;

    float4 px[2], pv[2];
    {
        int t = tb, b = t >> 7, s0 = (t & 127) * 64;
        const float4* kp = (const float4*)(key   + ((size_t)b * SN + s0) * FF);
        const float4* vp = (const float4*)(value + ((size_t)b * SN + s0) * FF);
#pragma unroll
        for (int q = 0; q < 2; ++q) { px[q] = kp[tid + q * 512]; pv[q] = vp[tid + q * 512]; }
    }

    for (int t = tb; t < te; ++t) {
        /* no barrier: stage buffers' last readers precede prev A-ready barrier */
#pragma unroll
        for (int q = 0; q < 2; ++q) {
            int r = ldr + q * 32;
            float4 xv = px[q];
            int p0 = (tid & 15) * 2;
            uint32_t h0 = pack_hi(xv.x, xv.y), h1 = pack_hi(xv.z, xv.w);
            uint32_t l0 = pack_lo(xv.x, xv.y, h0), l1 = pack_lo(xv.z, xv.w, h1);
            *(uint2*)(smc + KOFF_XT + (size_t)(r * 68 + p0) * 4)      = make_uint2(h0, h1);
            *(uint2*)(smc + KOFF_XT + (size_t)(r * 68 + 32 + p0) * 4) = make_uint2(l0, l1);
            *(float4*)&v_s[r * 68 + ldc] = pv[q];
            float sq = xv.x * xv.x + xv.y * xv.y + xv.z * xv.z + xv.w * xv.w;
#pragma unroll
            for (int d = 1; d < 16; d <<= 1)
                sq += __shfl_xor_sync(0xffffffffu, sq, d);
            if ((tid & 15) == 0) ssq_s[r] = 0.5f * sq;
        }
        if (t + 1 < te) {
            int tn = t + 1, b = tn >> 7, s0 = (tn & 127) * 64;
            const float4* kp = (const float4*)(key   + ((size_t)b * SN + s0) * FF);
            const float4* vp = (const float4*)(value + ((size_t)b * SN + s0) * FF);
#pragma unroll
            for (int q = 0; q < 2; ++q) { px[q] = kp[tid + q * 512]; pv[q] = vp[tid + q * 512]; }
        }
        __syncthreads();   /* XT, v, ssq ready; prev kv-MMA complete */

#pragma unroll
        for (int q = 0; q < 4; ++q) {
            int idx = tid + q * 512;
            int p = idx >> 6, n = idx & 63;
            float v0 = v_s[(2 * p) * 68 + n];
            float v1 = v_s[(2 * p + 1) * 68 + n];
            uint32_t hw = pack_hi(v0, v1);
            BT[n * 68 + p]      = hw;
            BT[n * 68 + 32 + p] = pack_lo(v0, v1, hw);
        }

#pragma unroll
        for (int nt4 = 0; nt4 < 4; ++nt4) {
            const int nt = ntb + nt4;
            float wa[4] = {0.f, 0.f, 0.f, 0.f};
#pragma unroll
            for (int kt = 0; kt < 4; ++kt) {
                uint32_t bh0, bh1, bl0, bl1;
                ldsm_x4(bh0, bh1, bl0, bl1, xtB + nt * 2176 + kt * 32);
                mma_bf16(wa, wfh[kt][0], wfh[kt][1], wfh[kt][2], wfh[kt][3], bh0, bh1);
                mma_bf16(wa, wfl[kt][0], wfl[kt][1], wfl[kt][2], wfl[kt][3], bh0, bh1);
                mma_bf16(wa, wfh[kt][0], wfh[kt][1], wfh[kt][2], wfh[kt][3], bl0, bl1);
            }
            const int r0 = nt * 8 + 2 * tg;
            const float sc0 = ssq_s[r0];
            const float sc1 = ssq_s[r0 + 1];
#pragma unroll
            for (int half = 0; half < 2; ++half) {
                int m = mt * 16 + gid + 8 * half;
                float w0 = wa[2 * half], w1 = wa[2 * half + 1];
                float e0 = (__expf(w0 - sc0) + EPSF) * SCALEF;
                float e1 = (__expf(w1 - sc1) + EPSF) * SCALEF;
                float g0 = (__expf(-w0 - sc0) + EPSF) * SCALEF;
                float g1 = (__expf(-w1 - sc1) + EPSF) * SCALEF;
                uint32_t he = pack_hi(e0, e1);
                uint32_t hg = pack_hi(g0, g1);
                *(uint32_t*)(smc + KOFF_AH + m * 144 + r0 * 2)         = he;
                *(uint32_t*)(smc + KOFF_AL + m * 144 + r0 * 2)         = pack_lo(e0, e1, he);
                *(uint32_t*)(smc + KOFF_AH + (m + 128) * 144 + r0 * 2) = hg;
                *(uint32_t*)(smc + KOFF_AL + (m + 128) * 144 + r0 * 2) = pack_lo(g0, g1, hg);
            }
        }
        __syncthreads();   /* A_phi, BT ready */

#pragma unroll
        for (int kt = 0; kt < 4; ++kt) {
            uint32_t ah0, ah1, ah2, ah3, al0, al1, al2, al3;
            ldsm_x4(ah0, ah1, ah2, ah3, aBase + kt * 32);
            ldsm_x4(al0, al1, al2, al3, aBase + (KOFF_AL - KOFF_AH) + kt * 32);
#pragma unroll
            for (int nt = 0; nt < 8; ++nt) {
                uint32_t bh0, bh1, bl0, bl1;
                ldsm_x4(bh0, bh1, bl0, bl1, btB + nt * 2176 + kt * 32);
                mma_bf16(acc[nt], ah0, ah1, ah2, ah3, bh0, bh1);
                mma_bf16(acc[nt], al0, al1, al2, al3, bh0, bh1);
                mma_bf16(acc[nt], ah0, ah1, ah2, ah3, bl0, bl1);
            }
            mma_bf16(accN, ah0, ah1, ah2, ah3, bnc, bnc);
            mma_bf16(accN, al0, al1, al2, al3, bnc, bnc);
        }

        if (t + 1 == te || ((t + 1) >> 7) != (t >> 7)) {
            float* base = &g_part[(size_t)(blk * 2 + seg) * TWOM * KVW];
            const int f0 = w * 16 + gid;
#pragma unroll
            for (int nt = 0; nt < 8; ++nt) {
                int c = nt * 8 + 2 * tg;
                *(float2*)&base[f0 * KVW + c]       = make_float2(acc[nt][0], acc[nt][1]);
                *(float2*)&base[(f0 + 8) * KVW + c] = make_float2(acc[nt][2], acc[nt][3]);
            }
            if (tg == 0) {
                base[f0 * KVW + 64]       = accN[0];
                base[(f0 + 8) * KVW + 64] = accN[2];
            }
            ++seg;
#pragma unroll
            for (int nt = 0; nt < 8; ++nt)
#pragma unroll
                for (int p = 0; p < 4; ++p) acc[nt][p] = 0.f;
#pragma unroll
            for (int p = 0; p < 4; ++p) accN[p] = 0.f;
        }
    }
}

// ---------------------------------------------------------------------------
// Kernel 2: deterministic reduction with ANALYTIC contributor range
// (only ~21 blocks can intersect batch b instead of scanning all 148).
// ---------------------------------------------------------------------------
__global__ void reduce_kernel() {
    const int per_b4 = TWOM * KVW / 4;
    int idx = blockIdx.x * blockDim.x + threadIdx.x;
    int b = blockIdx.y;
    if (idx >= per_b4) return;
    int ilo = (int)(((long long)b * 128 * NBLK) / NTILES) - 1;
    int ihi = (int)(((long long)(b + 1) * 128 * NBLK) / NTILES) + 2;
    if (ilo < 0) ilo = 0;
    if (ihi > NBLK) ihi = NBLK;
    float4 s = make_float4(0.f, 0.f, 0.f, 0.f);
    for (int i = ilo; i < ihi; ++i) {
        int tb = (i * NTILES) / NBLK;
        int te = ((i + 1) * NTILES) / NBLK;
        int b0 = tb >> 7;
        int bl = (te - 1) >> 7;
        int slot = (b0 == b) ? 0 : ((bl == b && bl != b0) ? 1 : -1);
        if (slot >= 0) {
            float4 v = ((const float4*)g_part)[(size_t)(i * 2 + slot) * per_b4 + idx];
            s.x += v.x; s.y += v.y; s.z += v.z; s.w += v.w;
        }
    }
    ((float4*)g_kv)[(size_t)b * per_b4 + idx] = s;
}

// ---------------------------------------------------------------------------
// Kernel 3: qkv with 16x16 warp tiles in the qkv-MMA (warp = rg4 x cg4):
// A-fragment sharing 8x -> 4x, balancing A/B smem traffic. Norm distributed
// as kt in {4*cg4..+3} per warp (uniform, full 3-term). Rest round-15 proven.
// ---------------------------------------------------------------------------
__global__ __launch_bounds__(512, 1)
void qkv_kernel(const float* __restrict__ query,
                const float* __restrict__ omega,
                float* __restrict__ out) {
    extern __shared__ char smc[];
    const uint32_t sb = smem_u32(smc);
    float* ssq_s  = (float*)(smc + QOFF_SQ);
    float* ns_s   = (float*)(smc + QOFF_NS);
    float* npb_s  = (float*)(smc + QOFF_NPB);
    uint32_t* BT  = (uint32_t*)(smc + QOFF_BT);

    const int tid = threadIdx.x;
    const int blk = blockIdx.x;
    const int tb = (blk * QUNITS) / QNB;
    const int te = ((blk + 1) * QUNITS) / QNB;

    {
        const float4* om4 = (const float4*)omega;
#pragma unroll
        for (int q = 0; q < 4; ++q) {
            int idx = tid + q * 512;
            float4 v = om4[idx];
            int m = idx >> 4, f = (idx & 15) * 4;
            uint32_t h01 = pack_hi(v.x, v.y), h23 = pack_hi(v.z, v.w);
            uint32_t* wh = (uint32_t*)(smc + QOFF_PH + m * 144 + f * 2);
            uint32_t* wl = (uint32_t*)(smc + QOFF_PL + m * 144 + f * 2);
            wh[0] = h01; wh[1] = h23;
            wl[0] = pack_lo(v.x, v.y, h01); wl[1] = pack_lo(v.z, v.w, h23);
        }
    }
    __syncthreads();

    const int w = tid >> 5, lane = tid & 31;
    const int gid = lane >> 2, tg = lane & 3;
    const int quad = lane >> 3, lrow = lane & 7;
    const int arow = lrow + (quad & 1) * 8;
    const int acolb = (quad >> 1) * 16;
    const int krow = lrow + (quad >> 1) * 8;
    const int mcol = (quad & 1) * 8;
    const int ldr = tid >> 4;
    const int mt = w >> 1;
    const int ntb = (w & 1) * 4;
    const int rg4m = w & 3;       /* qkv-MMA: rows rg4m*16..+15 */
    const int cg4  = w >> 2;      /* qkv-MMA: cols cg4*16..+15  */
    const uint32_t xq_lane = (uint32_t)((lane & 7) * 272 + ((lane >> 3) & 1) * 16 + (lane >> 4) * 128);
    const uint32_t bq_lane = (uint32_t)((lane & 7) * 1040 + ((lane >> 3) & 1) * 16 + (lane >> 4) * 512);
    const uint32_t xtB = sb + QOFF_XT + xq_lane;
    const uint32_t btB = sb + QOFF_BT + bq_lane;

    uint32_t wfh[4][4], wfl[4][4];
    {
        uint32_t obase = sb + QOFF_PH + (uint32_t)((mt * 16 + arow) * 144 + acolb);
#pragma unroll
        for (int kt = 0; kt < 4; ++kt) {
            ldsm_x4(wfh[kt][0], wfh[kt][1], wfh[kt][2], wfh[kt][3], obase + kt * 32);
            ldsm_x4(wfl[kt][0], wfl[kt][1], wfl[kt][2], wfl[kt][3],
                    obase + (QOFF_PL - QOFF_PH) + kt * 32);
        }
    }

    int cur_b = -1;
    float4 px[2];
    {
        int t = tb, b = t >> 7, r0 = (t & 127) * 64;
        const float4* qp = (const float4*)(query + ((size_t)b * TT + r0) * FF);
#pragma unroll
        for (int q = 0; q < 2; ++q) px[q] = qp[tid + q * 512];
    }

    for (int t = tb; t < te; ++t) {
        const int b = t >> 7;
        const int r0 = (t & 127) * 64;

        if (b != cur_b) {
            /* BT rebuild; prior qkv-MMA reads precede prev partials barrier */
            const float* kvp = &g_kv[(size_t)b * TWOM * KVW];
            for (int i = tid; i < 128 * 64; i += 512) {
                int p = i >> 6, n = i & 63;
                float v0 = kvp[(2 * p) * KVW + n];
                float v1 = kvp[(2 * p + 1) * KVW + n];
                uint32_t hw = pack_hi(v0, v1);
                BT[n * 260 + p]       = hw;
                BT[n * 260 + 128 + p] = pack_lo(v0, v1, hw);
            }
            if (tid < 128) {
                int p = tid;
                float v0 = kvp[(2 * p) * KVW + 64];
                float v1 = kvp[(2 * p + 1) * KVW + 64];
                uint32_t hw = pack_hi(v0, v1);
                BT[64 * 260 + p]       = hw;
                BT[64 * 260 + 128 + p] = pack_lo(v0, v1, hw);
            }
            for (int i = tid; i < 7 * 256; i += 512) {
                int r = 65 + (i >> 8), wd = i & 255;
                BT[r * 260 + wd] = 0u;
            }
            cur_b = b;
        }

        /* stage x -> XT hi/lo + ssq (no top barrier; audited) */
#pragma unroll
        for (int q = 0; q < 2; ++q) {
            int r = ldr + q * 32;
            float4 xv = px[q];
            int p0 = (tid & 15) * 2;
            uint32_t h0 = pack_hi(xv.x, xv.y), h1 = pack_hi(xv.z, xv.w);
            uint32_t l0 = pack_lo(xv.x, xv.y, h0), l1 = pack_lo(xv.z, xv.w, h1);
            *(uint2*)(smc + QOFF_XT + (size_t)(r * 68 + p0) * 4)      = make_uint2(h0, h1);
            *(uint2*)(smc + QOFF_XT + (size_t)(r * 68 + 32 + p0) * 4) = make_uint2(l0, l1);
            float sq = xv.x * xv.x + xv.y * xv.y + xv.z * xv.z + xv.w * xv.w;
#pragma unroll
            for (int d = 1; d < 16; d <<= 1)
                sq += __shfl_xor_sync(0xffffffffu, sq, d);
            if ((tid & 15) == 0) ssq_s[r] = 0.5f * sq;
        }
        if (t + 1 < te) {
            int tn = t + 1, bn = tn >> 7, rn = (tn & 127) * 64;
            const float4* qp = (const float4*)(query + ((size_t)bn * TT + rn) * FF);
#pragma unroll
            for (int q = 0; q < 2; ++q) px[q] = qp[tid + q * 512];
        }
        __syncthreads();   /* XT, ssq (and BT after rebuild) ready */

        /* phi-MMA + exp + phiT store */
#pragma unroll
        for (int nt4 = 0; nt4 < 4; ++nt4) {
            const int ntp = ntb + nt4;
            float wa[4] = {0.f, 0.f, 0.f, 0.f};
#pragma unroll
            for (int kt = 0; kt < 4; ++kt) {
                uint32_t bh0, bh1, bl0, bl1;
                ldsm_x4(bh0, bh1, bl0, bl1, xtB + ntp * 2176 + kt * 32);
                mma_bf16(wa, wfh[kt][0], wfh[kt][1], wfh[kt][2], wfh[kt][3], bh0, bh1);
                mma_bf16(wa, wfl[kt][0], wfl[kt][1], wfl[kt][2], wfl[kt][3], bh0, bh1);
                mma_bf16(wa, wfh[kt][0], wfh[kt][1], wfh[kt][2], wfh[kt][3], bl0, bl1);
            }
            const int rr = ntp * 8 + 2 * tg;
            const float sc0 = ssq_s[rr];
            const float sc1 = ssq_s[rr + 1];
#pragma unroll
            for (int half = 0; half < 2; ++half) {
                int m = mt * 16 + gid + 8 * half;
                float w0 = wa[2 * half], w1 = wa[2 * half + 1];
                float e0 = (__expf(w0 - sc0) + EPSF) * SCALEF;
                float e1 = (__expf(w1 - sc1) + EPSF) * SCALEF;
                float g0 = (__expf(-w0 - sc0) + EPSF) * SCALEF;
                float g1 = (__expf(-w1 - sc1) + EPSF) * SCALEF;
                uint32_t he = pack_hi(e0, e1);
                uint32_t hg = pack_hi(g0, g1);
                *(uint32_t*)(smc + QOFF_PH + m * 144 + rr * 2)         = he;
                *(uint32_t*)(smc + QOFF_PL + m * 144 + rr * 2)         = pack_lo(e0, e1, he);
                *(uint32_t*)(smc + QOFF_PH + (m + 128) * 144 + rr * 2) = hg;
                *(uint32_t*)(smc + QOFF_PL + (m + 128) * 144 + rr * 2) = pack_lo(g0, g1, hg);
            }
        }
        __syncthreads();   /* phiT ready */

        /* qkv-MMA, 16x16 warp tile: rows rg4m*16..+15, cols cg4*16..+15.
           Norm: this warp covers kt in {4*cg4 .. 4*cg4+3}, full 3-term. */
        float acc[2][4];
        float accN[4] = {0.f, 0.f, 0.f, 0.f};
#pragma unroll
        for (int cb = 0; cb < 2; ++cb)
#pragma unroll
            for (int p = 0; p < 4; ++p) acc[cb][p] = 0.f;

#pragma unroll
        for (int kt = 0; kt < 16; ++kt) {
            uint32_t bh0, bh1, bl0, bl1, ch0, ch1, cl0, cl1;
            ldsm_x4(bh0, bh1, bl0, bl1, btB + (2 * cg4) * 8320 + kt * 32);
            ldsm_x4(ch0, ch1, cl0, cl1, btB + (2 * cg4 + 1) * 8320 + kt * 32);
            const bool isn = ((kt >> 2) == cg4);   /* compile-time after unroll */
            uint32_t bn0 = 0, bn1 = 0, bm0 = 0, bm1 = 0;
            if (isn) ldsm_x4(bn0, bn1, bm0, bm1, btB + 64 * 1040 + kt * 32);

            uint32_t aaddr = sb + QOFF_PH +
                (uint32_t)((kt * 16 + krow) * 144 + (rg4m * 16 + mcol) * 2);
            uint32_t laddr = aaddr + (QOFF_PL - QOFF_PH);
            uint32_t a0, a1, a2, a3, l0, l1, l2, l3;
            ldsm_x4_t(a0, a1, a2, a3, aaddr);
            ldsm_x4_t(l0, l1, l2, l3, laddr);

            mma_bf16(acc[0], a0, a1, a2, a3, bh0, bh1);
            mma_bf16(acc[0], l0, l1, l2, l3, bh0, bh1);
            mma_bf16(acc[0], a0, a1, a2, a3, bl0, bl1);
            mma_bf16(acc[1], a0, a1, a2, a3, ch0, ch1);
            mma_bf16(acc[1], l0, l1, l2, l3, ch0, ch1);
            mma_bf16(acc[1], a0, a1, a2, a3, cl0, cl1);
            if (isn) {
                mma_bf16(accN, a0, a1, a2, a3, bn0, bn1);
                mma_bf16(accN, l0, l1, l2, l3, bn0, bn1);
                mma_bf16(accN, a0, a1, a2, a3, bm0, bm1);
            }
        }
        if (tg == 0) {
            npb_s[cg4 * 66 + rg4m * 16 + gid]     = accN[0];
            npb_s[cg4 * 66 + rg4m * 16 + gid + 8] = accN[2];
        }
        __syncthreads();   /* partials ready */
        if (tid < 64) {
            float s = 0.f;
#pragma unroll
            for (int j = 0; j < 4; ++j) s += npb_s[j * 66 + tid];
            ns_s[tid] = s;
        }
        __syncthreads();   /* norm ready */

        /* epilogue */
        {
            int row0 = rg4m * 16 + gid, row1 = row0 + 8;
            float inv0 = 1.0f / ns_s[row0];
            float inv1 = 1.0f / ns_s[row1];
            float* o0 = out + ((size_t)b * TT + r0 + row0) * DD + cg4 * 16 + 2 * tg;
            float* o1 = out + ((size_t)b * TT + r0 + row1) * DD + cg4 * 16 + 2 * tg;
            *(float2*)o0       = make_float2(acc[0][0] * inv0, acc[0][1] * inv0);
            *(float2*)(o0 + 8) = make_float2(acc[1][0] * inv0, acc[1][1] * inv0);
            *(float2*)o1       = make_float2(acc[0][2] * inv1, acc[0][3] * inv1);
            *(float2*)(o1 + 8) = make_float2(acc[1][2] * inv1, acc[1][3] * inv1);
        }
    }
}

// ---------------------------------------------------------------------------

extern "C" void kernel_launch(void* const* d_in, const int* in_sizes, int n_in,
                              void* d_out, int out_size) {
    const float* query = (const float*)d_in[0];
    const float* value = (const float*)d_in[1];
    const float* key   = (const float*)d_in[2];
    const float* omega = (const float*)d_in[3];
    float* out = (float*)d_out;

    cudaFuncSetAttribute(kv_kernel, cudaFuncAttributeMaxDynamicSharedMemorySize, KV_SMEM);
    cudaFuncSetAttribute(qkv_kernel, cudaFuncAttributeMaxDynamicSharedMemorySize, QSMEM);

    kv_kernel<<<NBLK, 512, KV_SMEM>>>(key, value, omega);
    reduce_kernel<<<dim3((TWOM * KVW / 4 + 255) / 256, BB), 256>>>();
    qkv_kernel<<<QNB, 512, QSMEM>>>(query, omega, out);
}